// round 1
// baseline (speedup 1.0000x reference)
#include <cuda_runtime.h>

#define BB   8
#define CIN  32
#define COUT 32
#define HH   128
#define WW   128
#define SS   1024
#define JJ   (HH*WW)

// Scratch: overwritten every launch (no cross-replay state, no zeroing needed).
__device__ float g_T[BB*CIN];
__device__ float g_U[BB*CIN];
__device__ float g_V[BB*CIN];

// Kernel A: one block per (b,i). 256 threads x 4 samples = S=1024.
// T = sum_s v[b,i,idx_s]; U = sum_s x_s * v; V = sum_s y_s * v.
__global__ void __launch_bounds__(256) nystrom_reduce_tuv(
    const float* __restrict__ v,
    const int*   __restrict__ idx32)   // raw view; dtype detected below
{
    const int bi  = blockIdx.x;            // b*32 + i
    const float* plane = v + (size_t)bi * JJ;
    const int tid = threadIdx.x;

    // dtype detection: indices are a permutation (distinct values in [0,16384)).
    // int32 data can have at most ONE zero among idx[1],idx[3],idx[5];
    // int64 data has zero high-words at odd int32 positions always.
    const bool is64 = (idx32[1] == 0) && (idx32[3] == 0) && (idx32[5] == 0);

    const float step = 2.0f / 127.0f;
    float t = 0.f, u = 0.f, w = 0.f;

    #pragma unroll
    for (int k = 0; k < 4; ++k) {
        const int s = tid + k * 256;
        const int j = is64 ? idx32[2 * s] : idx32[s];   // values < 2^31, low word suffices
        const int jw = j & (WW - 1);
        const int jh = j >> 7;
        const float x = -1.0f + step * (float)jw;
        const float y = -1.0f + step * (float)jh;
        const float val = __ldg(plane + j);
        t += val;
        u += x * val;
        w += y * val;
    }

    // warp reduce
    #pragma unroll
    for (int off = 16; off > 0; off >>= 1) {
        t += __shfl_down_sync(0xffffffffu, t, off);
        u += __shfl_down_sync(0xffffffffu, u, off);
        w += __shfl_down_sync(0xffffffffu, w, off);
    }
    __shared__ float st[8], su[8], sw[8];
    const int warp = tid >> 5, lane = tid & 31;
    if (lane == 0) { st[warp] = t; su[warp] = u; sw[warp] = w; }
    __syncthreads();
    if (tid == 0) {
        float T = 0.f, U = 0.f, V = 0.f;
        #pragma unroll
        for (int q = 0; q < 8; ++q) { T += st[q]; U += su[q]; V += sw[q]; }
        g_T[bi] = T; g_U[bi] = U; g_V[bi] = V;
    }
}

// Kernel B: output fill. 4 blocks per (b,o) plane; 256 threads x 4 float4 each.
// u[b,o,h,w] = x_w * P + y_h * Q - R
__global__ void __launch_bounds__(256) nystrom_fill(
    const float* __restrict__ weight,   // [COUT, CIN, 2]
    float*       __restrict__ out)      // [B, COUT, H, W]
{
    const int plane = blockIdx.x >> 2;   // b*32 + o
    const int chunk = blockIdx.x & 3;    // 4096-float chunk within plane
    const int b = plane >> 5;
    const int o = plane & 31;
    const int tid = threadIdx.x;

    __shared__ float sP, sQ, sR;
    if (tid == 0) {
        float P = 0.f, Q = 0.f, R = 0.f;
        const float* wr = weight + o * (CIN * 2);
        const float* T = g_T + b * CIN;
        const float* U = g_U + b * CIN;
        const float* V = g_V + b * CIN;
        #pragma unroll
        for (int i = 0; i < CIN; ++i) {
            const float w0 = wr[2 * i], w1 = wr[2 * i + 1];
            P += T[i] * w0;
            Q += T[i] * w1;
            R += U[i] * w0 + V[i] * w1;
        }
        sP = P; sQ = Q; sR = R;
    }
    __syncthreads();
    const float P = sP, Q = sQ, R = sR;

    const float step = 2.0f / 127.0f;
    float4* outp = (float4*)(out + (size_t)plane * JJ + chunk * 4096);

    #pragma unroll
    for (int k = 0; k < 4; ++k) {
        const int q4 = tid + k * 256;          // float4 index within chunk [0,1024)
        const int r  = chunk * 4096 + q4 * 4;  // linear index within plane
        const int h  = r >> 7;
        const int wq = r & (WW - 1);
        const float y = -1.0f + step * (float)h;
        const float base = fmaf(y, Q, -R);
        const float x0 = -1.0f + step * (float)wq;
        float4 o4;
        o4.x = fmaf(x0,               P, base);
        o4.y = fmaf(x0 +        step, P, base);
        o4.z = fmaf(x0 + 2.0f * step, P, base);
        o4.w = fmaf(x0 + 3.0f * step, P, base);
        outp[q4] = o4;
    }
}

extern "C" void kernel_launch(void* const* d_in, const int* in_sizes, int n_in,
                              void* d_out, int out_size)
{
    const float* v      = (const float*)d_in[0];
    const float* weight = (const float*)d_in[1];
    const int*   idx32  = (const int*)  d_in[2];   // int32 or int64 detected in-kernel
    float*       out    = (float*)d_out;

    nystrom_reduce_tuv<<<BB * CIN, 256>>>(v, idx32);
    nystrom_fill<<<BB * COUT * 4, 256>>>(weight, out);
}

// round 2
// speedup vs baseline: 1.1866x; 1.1866x over previous
#include <cuda_runtime.h>

#define BB   8
#define CIN  32
#define COUT 32
#define HH   128
#define WW   128
#define SS   1024
#define JJ   (HH*WW)

// Scratch: fully overwritten every launch (deterministic across graph replays).
__device__ float g_T[BB*CIN];
__device__ float g_U[BB*CIN];
__device__ float g_V[BB*CIN];

// Kernel A: one block per (b,i). 256 threads x 4 samples = S=1024.
// T = sum_s v[b,i,idx_s]; U = sum_s x_s * v; V = sum_s y_s * v.
__global__ void __launch_bounds__(256) nystrom_reduce_tuv(
    const float* __restrict__ v,
    const int*   __restrict__ idx32)   // raw view; dtype detected below
{
    const int bi  = blockIdx.x;            // b*32 + i
    const float* plane = v + (size_t)bi * JJ;
    const int tid = threadIdx.x;

    // dtype detection: indices are a permutation (distinct values), so three
    // zero words at int32 positions 1,3,5 can only be int64 high-halves.
    const bool is64 = (idx32[1] == 0) && (idx32[3] == 0) && (idx32[5] == 0);

    const float step = 2.0f / 127.0f;
    float t = 0.f, u = 0.f, w = 0.f;

    #pragma unroll
    for (int k = 0; k < 4; ++k) {
        const int s = tid + k * 256;
        const int j = is64 ? idx32[2 * s] : idx32[s];
        const int jw = j & (WW - 1);
        const int jh = j >> 7;
        const float x = -1.0f + step * (float)jw;
        const float y = -1.0f + step * (float)jh;
        const float val = __ldg(plane + j);
        t += val;
        u  = fmaf(x, val, u);
        w  = fmaf(y, val, w);
    }

    #pragma unroll
    for (int off = 16; off > 0; off >>= 1) {
        t += __shfl_down_sync(0xffffffffu, t, off);
        u += __shfl_down_sync(0xffffffffu, u, off);
        w += __shfl_down_sync(0xffffffffu, w, off);
    }
    __shared__ float st[8], su[8], sw[8];
    const int warp = tid >> 5, lane = tid & 31;
    if (lane == 0) { st[warp] = t; su[warp] = u; sw[warp] = w; }
    __syncthreads();
    if (tid == 0) {
        float T = 0.f, U = 0.f, V = 0.f;
        #pragma unroll
        for (int q = 0; q < 8; ++q) { T += st[q]; U += su[q]; V += sw[q]; }
        g_T[bi] = T; g_U[bi] = U; g_V[bi] = V;
    }
}

// Kernel B: output fill. 4 blocks per (b,o) plane; 256 threads x 4 float4 each.
// P/Q/R dot computed warp-redundantly (lane = channel): no smem, no barrier.
// u[b,o,h,w] = x_w * P + y_h * Q - R
__global__ void __launch_bounds__(256) nystrom_fill(
    const float* __restrict__ weight,   // [COUT, CIN, 2]
    float*       __restrict__ out)      // [B, COUT, H, W]
{
    const int plane = blockIdx.x >> 2;   // b*32 + o
    const int chunk = blockIdx.x & 3;    // 4096-float chunk within plane
    const int b = plane >> 5;
    const int o = plane & 31;
    const int tid  = threadIdx.x;
    const int lane = tid & 31;

    // Warp-parallel 32-term dot: lane i owns channel i.
    const float T = g_T[b * CIN + lane];
    const float U = g_U[b * CIN + lane];
    const float V = g_V[b * CIN + lane];
    const float2 wv = ((const float2*)weight)[o * CIN + lane];

    float p = T * wv.x;
    float q = T * wv.y;
    float r = fmaf(U, wv.x, V * wv.y);
    #pragma unroll
    for (int off = 16; off > 0; off >>= 1) {
        p += __shfl_xor_sync(0xffffffffu, p, off);
        q += __shfl_xor_sync(0xffffffffu, q, off);
        r += __shfl_xor_sync(0xffffffffu, r, off);
    }
    const float P = p, Q = q, R = r;

    const float step = 2.0f / 127.0f;
    float4* outp = (float4*)(out + (size_t)plane * JJ + chunk * 4096);

    #pragma unroll
    for (int k = 0; k < 4; ++k) {
        const int q4 = tid + k * 256;          // float4 index within chunk
        const int rr = chunk * 4096 + q4 * 4;  // linear index within plane
        const int h  = rr >> 7;
        const int wq = rr & (WW - 1);
        const float y = -1.0f + step * (float)h;
        const float base = fmaf(y, Q, -R);
        const float x0 = -1.0f + step * (float)wq;
        float4 o4;
        o4.x = fmaf(x0,               P, base);
        o4.y = fmaf(x0 +        step, P, base);
        o4.z = fmaf(x0 + 2.0f * step, P, base);
        o4.w = fmaf(x0 + 3.0f * step, P, base);
        outp[q4] = o4;
    }
}

extern "C" void kernel_launch(void* const* d_in, const int* in_sizes, int n_in,
                              void* d_out, int out_size)
{
    const float* v      = (const float*)d_in[0];
    const float* weight = (const float*)d_in[1];
    const int*   idx32  = (const int*)  d_in[2];   // int32 or int64, detected in-kernel
    float*       out    = (float*)d_out;

    nystrom_reduce_tuv<<<BB * CIN, 256>>>(v, idx32);
    nystrom_fill<<<BB * COUT * 4, 256>>>(weight, out);
}

// round 3
// speedup vs baseline: 1.2186x; 1.0269x over previous
#include <cuda_runtime.h>

#define BB   8
#define CIN  32
#define COUT 32
#define HH   128
#define WW   128
#define SS   1024
#define JJ   (HH*WW)
#define NB   128          // persistent blocks: <= 148 SMs @ 1 CTA/SM -> all co-resident
#define NT   256

// Scratch (overwritten every launch) + monotone barrier counter (never reset;
// each launch adds exactly NB, so epoch targets are multiples of NB).
__device__ float g_T[BB*CIN];
__device__ float g_U[BB*CIN];
__device__ float g_V[BB*CIN];
__device__ unsigned int g_bar;   // zero-initialized at module load

__global__ void __launch_bounds__(NT, 1) nystrom_fused(
    const float* __restrict__ v,        // [B, CIN, H, W]
    const float* __restrict__ weight,   // [COUT, CIN, 2]
    const int*   __restrict__ idx32,    // int32 or int64 (detected)
    float*       __restrict__ out)      // [B, COUT, H, W]
{
    const int tid  = threadIdx.x;
    const int lane = tid & 31;
    const int warp = tid >> 5;
    const float step = 2.0f / 127.0f;

    // indices are a permutation (distinct); three zeros at int32 positions
    // 1,3,5 can only be int64 high-halves.
    const bool is64 = (idx32[1] == 0) && (idx32[3] == 0) && (idx32[5] == 0);

    __shared__ float sred[3][8];

    // ---------------- Phase 1: gather-reduce T/U/V for 2 (b,i) tasks ----------
    #pragma unroll
    for (int tsk = 0; tsk < 2; ++tsk) {
        const int bi = blockIdx.x * 2 + tsk;     // 0..255
        const float* plane = v + (size_t)bi * JJ;

        float t = 0.f, u = 0.f, w = 0.f;
        #pragma unroll
        for (int k = 0; k < 4; ++k) {
            const int s = tid + k * NT;
            const int j = is64 ? idx32[2 * s] : idx32[s];
            const float x = -1.0f + step * (float)(j & (WW - 1));
            const float y = -1.0f + step * (float)(j >> 7);
            const float val = __ldg(plane + j);
            t += val;
            u  = fmaf(x, val, u);
            w  = fmaf(y, val, w);
        }
        #pragma unroll
        for (int off = 16; off > 0; off >>= 1) {
            t += __shfl_down_sync(0xffffffffu, t, off);
            u += __shfl_down_sync(0xffffffffu, u, off);
            w += __shfl_down_sync(0xffffffffu, w, off);
        }
        if (lane == 0) { sred[0][warp] = t; sred[1][warp] = u; sred[2][warp] = w; }
        __syncthreads();
        if (tid == 0) {
            float T = 0.f, U = 0.f, V = 0.f;
            #pragma unroll
            for (int q = 0; q < 8; ++q) { T += sred[0][q]; U += sred[1][q]; V += sred[2][q]; }
            g_T[bi] = T; g_U[bi] = U; g_V[bi] = V;
        }
        __syncthreads();
    }

    // ---------------- Grid barrier (epoch-based, replay-safe) -----------------
    if (tid == 0) {
        __threadfence();                                   // release T/U/V
        const unsigned int old = atomicAdd(&g_bar, 1u);
        const unsigned int target = (old / NB + 1u) * NB;  // end of this launch's epoch
        while (atomicAdd(&g_bar, 0u) < target) { __nanosleep(64); }
        __threadfence();                                   // acquire
    }
    __syncthreads();

    // ---------------- Phase 2: fill 2 output planes ---------------------------
    #pragma unroll
    for (int tsk = 0; tsk < 2; ++tsk) {
        const int pl = blockIdx.x * 2 + tsk;     // b*32 + o
        const int b = pl >> 5;
        const int o = pl & 31;

        // Warp-parallel dot: lane = channel. L2-only loads (skip stale L1).
        const float T = __ldcg(g_T + b * CIN + lane);
        const float U = __ldcg(g_U + b * CIN + lane);
        const float V = __ldcg(g_V + b * CIN + lane);
        const float2 wv = ((const float2*)weight)[o * CIN + lane];

        float p = T * wv.x;
        float q = T * wv.y;
        float r = fmaf(U, wv.x, V * wv.y);
        #pragma unroll
        for (int off = 16; off > 0; off >>= 1) {
            p += __shfl_xor_sync(0xffffffffu, p, off);
            q += __shfl_xor_sync(0xffffffffu, q, off);
            r += __shfl_xor_sync(0xffffffffu, r, off);
        }
        const float P = p, Q = q, R = r;

        float4* outp = (float4*)(out + (size_t)pl * JJ);
        #pragma unroll
        for (int k = 0; k < 16; ++k) {
            const int q4 = tid + k * NT;           // float4 index in plane [0,4096)
            const int h  = q4 >> 5;                // (q4*4) >> 7
            const int wq = (q4 * 4) & (WW - 1);
            const float y = -1.0f + step * (float)h;
            const float base = fmaf(y, Q, -R);
            const float x0 = -1.0f + step * (float)wq;
            float4 o4;
            o4.x = fmaf(x0,               P, base);
            o4.y = fmaf(x0 +        step, P, base);
            o4.z = fmaf(x0 + 2.0f * step, P, base);
            o4.w = fmaf(x0 + 3.0f * step, P, base);
            outp[q4] = o4;
        }
    }
}

extern "C" void kernel_launch(void* const* d_in, const int* in_sizes, int n_in,
                              void* d_out, int out_size)
{
    const float* v      = (const float*)d_in[0];
    const float* weight = (const float*)d_in[1];
    const int*   idx32  = (const int*)  d_in[2];
    float*       out    = (float*)d_out;

    nystrom_fused<<<NB, NT>>>(v, weight, idx32, out);
}